// round 1
// baseline (speedup 1.0000x reference)
#include <cuda_runtime.h>
#include <cstdint>

#define L_SEQ 2048
#define D_DIM 768
#define K_F   16
#define NFFT  4096
#define KU    3
#define C_CONV (2 * K_F * D_DIM)          // 24576
#define C_TOT  (C_CONV + KU * D_DIM)      // 26880
#define KTILES (C_TOT / 32)               // 840

// ---------------- static device scratch (no runtime allocation) ----------------
__device__ __align__(16) float  g_Ubig[(size_t)C_TOT * L_SEQ];   // (C, L) A^T layout
__device__ __align__(16) float  g_Mbig[(size_t)C_TOT * D_DIM];   // (C, O)
__device__ __align__(16) float2 g_Z[D_DIM * NFFT];               // fwd FFT of packed x
__device__ __align__(16) float2 g_V[K_F * NFFT];                 // fwd FFT of phi
__device__ __align__(16) float2 g_tw[NFFT];                      // exp(-2*pi*i*j/NFFT)

// ---------------- complex helpers ----------------
__device__ __forceinline__ float2 cadd(float2 a, float2 b) { return make_float2(a.x + b.x, a.y + b.y); }
__device__ __forceinline__ float2 csub(float2 a, float2 b) { return make_float2(a.x - b.x, a.y - b.y); }
__device__ __forceinline__ float2 cmul(float2 a, float2 b) {
    return make_float2(a.x * b.x - a.y * b.y, a.x * b.y + a.y * b.x);
}
__device__ __forceinline__ float2 cmulconj(float2 a, float2 w) {  // a * conj(w)
    return make_float2(a.x * w.x + a.y * w.y, a.y * w.x - a.x * w.y);
}

// ---------------- twiddle init ----------------
__global__ void k_twiddle() {
    int j = blockIdx.x * blockDim.x + threadIdx.x;
    if (j < NFFT) {
        float s, c;
        sincospif(-2.0f * (float)j / (float)NFFT, &s, &c);
        g_tw[j] = make_float2(c, s);
    }
}

// ---------------- in-place radix-4 DIF forward stages (shared) ----------------
__device__ __forceinline__ void fft_fwd_shared(float2* S, int tid) {
    #pragma unroll
    for (int s = 0; s < 6; s++) {
        int len = NFFT >> (2 * s);
        int q = len >> 2;
        int step = 1 << (2 * s);
        for (int idx = tid; idx < NFFT / 4; idx += 256) {
            int j = idx & (q - 1);
            int g = idx >> (10 - 2 * s);
            int base = (g << (12 - 2 * s)) + j;
            float2 a = S[base], b = S[base + q], c = S[base + 2 * q], d = S[base + 3 * q];
            float2 w1 = g_tw[j * step];
            float2 w2 = cmul(w1, w1);
            float2 w3 = cmul(w2, w1);
            float2 t0 = cadd(a, c), t1 = csub(a, c);
            float2 t2 = cadd(b, d), t3 = csub(b, d);
            float2 t3m = make_float2(t3.y, -t3.x);           // -i*(b-d)
            S[base]         = cadd(t0, t2);
            S[base + q]     = cmul(cadd(t1, t3m), w1);
            S[base + 2 * q] = cmul(csub(t0, t2), w2);
            S[base + 3 * q] = cmul(csub(t1, t3m), w3);
        }
        __syncthreads();
    }
}

// ---------------- in-place radix-4 DIT inverse stages (exact inverse of fwd) ----------------
__device__ __forceinline__ void fft_inv_shared(float2* S, int tid) {
    #pragma unroll
    for (int s = 5; s >= 0; s--) {
        int len = NFFT >> (2 * s);
        int q = len >> 2;
        int step = 1 << (2 * s);
        for (int idx = tid; idx < NFFT / 4; idx += 256) {
            int j = idx & (q - 1);
            int g = idx >> (10 - 2 * s);
            int base = (g << (12 - 2 * s)) + j;
            float2 w1 = g_tw[j * step];
            float2 w2 = cmul(w1, w1);
            float2 w3 = cmul(w2, w1);
            float2 u0 = S[base];
            float2 u1 = cmulconj(S[base + q], w1);
            float2 u2 = cmulconj(S[base + 2 * q], w2);
            float2 u3 = cmulconj(S[base + 3 * q], w3);
            float2 t0 = cadd(u0, u2), t1 = csub(u0, u2);
            float2 t2 = cadd(u1, u3), t3 = csub(u1, u3);
            float2 it3 = make_float2(-t3.y, t3.x);           // i*(u1-u3)
            S[base]         = cadd(t0, t2);
            S[base + q]     = cadd(t1, it3);
            S[base + 2 * q] = csub(t0, t2);
            S[base + 3 * q] = csub(t1, it3);
        }
        __syncthreads();
    }
}

// ---------------- forward FFT: 768 x-channels (packed +/-) + 16 phi channels ----------------
__global__ void __launch_bounds__(256) k_fft_fwd(const float* __restrict__ x,
                                                 const float* __restrict__ phi) {
    __shared__ float2 S[NFFT];
    int b = blockIdx.x;
    int tid = threadIdx.x;
    if (b < D_DIM) {
        int d = b;
        for (int t = tid; t < NFFT; t += 256) {
            float v = (t < L_SEQ) ? x[t * D_DIM + d] : 0.0f;
            float sg = (t & 1) ? -v : v;
            S[t] = make_float2(v, sg);
        }
    } else {
        int k = b - D_DIM;
        for (int t = tid; t < NFFT; t += 256)
            S[t] = make_float2((t < L_SEQ) ? phi[t * K_F + k] : 0.0f, 0.0f);
    }
    __syncthreads();
    fft_fwd_shared(S, tid);
    float2* out = (b < D_DIM) ? (g_Z + (size_t)b * NFFT) : (g_V + (size_t)(b - D_DIM) * NFFT);
    for (int t = tid; t < NFFT; t += 256) out[t] = S[t];
}

// ---------------- per-(k,d): pointwise V*Z, inverse FFT, scatter to Ubig ----------------
__global__ void __launch_bounds__(256) k_conv_inv() {
    __shared__ float2 S[NFFT];
    int b = blockIdx.x;              // 0 .. K_F*D_DIM-1
    int k = b / D_DIM;
    int d = b - k * D_DIM;
    int tid = threadIdx.x;
    const float2* Z = g_Z + (size_t)d * NFFT;
    const float2* V = g_V + (size_t)k * NFFT;
    for (int t = tid; t < NFFT; t += 256) S[t] = cmul(Z[t], V[t]);
    __syncthreads();
    fft_inv_shared(S, tid);
    const float inv = 1.0f / (float)NFFT;
    float* up = g_Ubig + (size_t)(k * D_DIM + d) * L_SEQ;
    float* um = g_Ubig + (size_t)(C_CONV / 2 + k * D_DIM + d) * L_SEQ;
    for (int t = tid; t < L_SEQ; t += 256) {
        float2 v = S[t];
        up[t] = v.x * inv;
        um[t] = ((t & 1) ? -v.y : v.y) * inv;
    }
}

// ---------------- AR channels: Ubig rows 24576.. hold shifted x ----------------
__global__ void __launch_bounds__(256) k_arfill(const float* __restrict__ x) {
    int c = blockIdx.x;              // 0 .. KU*D_DIM-1
    int i = c / D_DIM;
    int d = c - i * D_DIM;
    float* dst = g_Ubig + (size_t)(C_CONV + c) * L_SEQ;
    for (int l = threadIdx.x; l < L_SEQ; l += 256)
        dst[l] = (l >= i) ? x[(l - i) * D_DIM + d] : 0.0f;
}

// ---------------- pack [Mp*sig4 ; Mm*sig4 ; Mu] into (C_TOT, D) ----------------
__global__ void __launch_bounds__(256) k_mbig(const float* __restrict__ Mp,
                                              const float* __restrict__ Mm,
                                              const float* __restrict__ Mu,
                                              const float* __restrict__ sigma) {
    int c = blockIdx.x;
    const float* src;
    float scale;
    if (c < K_F * D_DIM) {
        int k = c / D_DIM;
        src = Mp + (size_t)c * D_DIM;
        scale = powf(sigma[k], 0.25f);
    } else if (c < 2 * K_F * D_DIM) {
        int cc = c - K_F * D_DIM;
        int k = cc / D_DIM;
        src = Mm + (size_t)cc * D_DIM;
        scale = powf(sigma[k], 0.25f);
    } else {
        int cc = c - 2 * K_F * D_DIM;
        src = Mu + (size_t)cc * D_DIM;
        scale = 1.0f;
    }
    for (int o = threadIdx.x; o < D_DIM; o += 256)
        g_Mbig[(size_t)c * D_DIM + o] = src[o] * scale;
}

// ---------------- TF32 GEMM: out[l,o] = sum_c Ubig[c,l] * Mbig[c,o] ----------------
__device__ __forceinline__ float to_tf32(float x) {
    float r;
    asm("cvt.rna.tf32.f32 %0, %1;" : "=f"(r) : "f"(x));
    return r;
}
__device__ __forceinline__ void mma_tf32(float* acc, const uint32_t* a, const uint32_t* b) {
    asm volatile(
        "mma.sync.aligned.m16n8k8.row.col.f32.tf32.tf32.f32 "
        "{%0,%1,%2,%3}, {%4,%5,%6,%7}, {%8,%9}, {%0,%1,%2,%3};"
        : "+f"(acc[0]), "+f"(acc[1]), "+f"(acc[2]), "+f"(acc[3])
        : "r"(a[0]), "r"(a[1]), "r"(a[2]), "r"(a[3]), "r"(b[0]), "r"(b[1]));
}

__global__ void __launch_bounds__(128) k_gemm(float* __restrict__ out) {
    __shared__ float As[32][72];  // [c][l], pitch 72 -> conflict-free fragment LDS
    __shared__ float Bs[32][72];  // [c][o]
    const int tid = threadIdx.x;
    const int lane = tid & 31, warp = tid >> 5;
    const int mbase = blockIdx.y * 64, nbase = blockIdx.x * 64;
    const int wm = (warp & 1) * 32, wn = (warp >> 1) * 32;
    const int row = lane >> 2, col = lane & 3;
    const int cl = tid >> 4;          // loader: base c row
    const int l4 = (tid & 15) * 4;    // loader: float4 offset within row

    float acc[2][4][4];
    #pragma unroll
    for (int mi = 0; mi < 2; mi++)
        #pragma unroll
        for (int ni = 0; ni < 4; ni++)
            #pragma unroll
            for (int r = 0; r < 4; r++) acc[mi][ni][r] = 0.0f;

    float4 ra[4], rb[4];

    auto LOADG = [&](int kt) {
        int kb = kt * 32;
        #pragma unroll
        for (int i = 0; i < 4; i++) {
            int c = cl + i * 8;
            ra[i] = *(const float4*)(g_Ubig + (size_t)(kb + c) * L_SEQ + mbase + l4);
            rb[i] = *(const float4*)(g_Mbig + (size_t)(kb + c) * D_DIM + nbase + l4);
        }
    };
    auto STORES = [&]() {
        #pragma unroll
        for (int i = 0; i < 4; i++) {
            int c = cl + i * 8;
            As[c][l4 + 0] = to_tf32(ra[i].x); As[c][l4 + 1] = to_tf32(ra[i].y);
            As[c][l4 + 2] = to_tf32(ra[i].z); As[c][l4 + 3] = to_tf32(ra[i].w);
            Bs[c][l4 + 0] = to_tf32(rb[i].x); Bs[c][l4 + 1] = to_tf32(rb[i].y);
            Bs[c][l4 + 2] = to_tf32(rb[i].z); Bs[c][l4 + 3] = to_tf32(rb[i].w);
        }
    };

    LOADG(0);
    STORES();
    __syncthreads();

    for (int kt = 0; kt < KTILES; kt++) {
        if (kt + 1 < KTILES) LOADG(kt + 1);
        #pragma unroll
        for (int ks = 0; ks < 4; ks++) {
            const int k8 = ks * 8;
            uint32_t a[2][4], bf[4][2];
            #pragma unroll
            for (int mi = 0; mi < 2; mi++) {
                int lb = wm + mi * 16 + row;
                a[mi][0] = __float_as_uint(As[k8 + col][lb]);
                a[mi][1] = __float_as_uint(As[k8 + col][lb + 8]);
                a[mi][2] = __float_as_uint(As[k8 + col + 4][lb]);
                a[mi][3] = __float_as_uint(As[k8 + col + 4][lb + 8]);
            }
            #pragma unroll
            for (int ni = 0; ni < 4; ni++) {
                int nb = wn + ni * 8 + row;
                bf[ni][0] = __float_as_uint(Bs[k8 + col][nb]);
                bf[ni][1] = __float_as_uint(Bs[k8 + col + 4][nb]);
            }
            #pragma unroll
            for (int mi = 0; mi < 2; mi++)
                #pragma unroll
                for (int ni = 0; ni < 4; ni++)
                    mma_tf32(acc[mi][ni], a[mi], bf[ni]);
        }
        __syncthreads();
        if (kt + 1 < KTILES) {
            STORES();
            __syncthreads();
        }
    }

    // epilogue: D = spectral + ar, row-major (L, D)
    #pragma unroll
    for (int mi = 0; mi < 2; mi++) {
        #pragma unroll
        for (int ni = 0; ni < 4; ni++) {
            int r0 = mbase + wm + mi * 16 + row;
            int c0 = nbase + wn + ni * 8 + col * 2;
            out[(size_t)r0 * D_DIM + c0]           = acc[mi][ni][0];
            out[(size_t)r0 * D_DIM + c0 + 1]       = acc[mi][ni][1];
            out[(size_t)(r0 + 8) * D_DIM + c0]     = acc[mi][ni][2];
            out[(size_t)(r0 + 8) * D_DIM + c0 + 1] = acc[mi][ni][3];
        }
    }
}

// ---------------- launch ----------------
extern "C" void kernel_launch(void* const* d_in, const int* in_sizes, int n_in,
                              void* d_out, int out_size) {
    const float* x     = (const float*)d_in[0];
    const float* phi   = (const float*)d_in[1];
    const float* sigma = (const float*)d_in[2];
    const float* Mp    = (const float*)d_in[3];
    const float* Mm    = (const float*)d_in[4];
    const float* Mu    = (const float*)d_in[5];
    (void)in_sizes; (void)n_in; (void)out_size;

    k_twiddle<<<NFFT / 256, 256>>>();
    k_fft_fwd<<<D_DIM + K_F, 256>>>(x, phi);
    k_conv_inv<<<K_F * D_DIM, 256>>>();
    k_arfill<<<KU * D_DIM, 256>>>(x);
    k_mbig<<<C_TOT, 256>>>(Mp, Mm, Mu, sigma);
    k_gemm<<<dim3(D_DIM / 64, L_SEQ / 64), 128>>>((float*)d_out);
}

// round 2
// speedup vs baseline: 1.0183x; 1.0183x over previous
#include <cuda_runtime.h>
#include <cstdint>

#define L_SEQ 2048
#define D_DIM 768
#define K_F   16
#define NFFT  4096
#define KU    3
#define C_CONV (2 * K_F * D_DIM)          // 24576
#define C_TOT  (C_CONV + KU * D_DIM)      // 26880
#define KTILES (C_TOT / 32)               // 840

// ---------------- static device scratch (no runtime allocation) ----------------
__device__ __align__(16) float  g_Ubig[(size_t)C_TOT * L_SEQ];   // (C, L) A^T layout
__device__ __align__(16) float  g_Mbig[(size_t)C_TOT * D_DIM];   // (C, O)
__device__ __align__(16) float2 g_Z[D_DIM * NFFT];               // fwd FFT of packed x
__device__ __align__(16) float2 g_V[K_F * NFFT];                 // fwd FFT of phi
__device__ __align__(16) float2 g_tw[NFFT];                      // exp(-2*pi*i*j/NFFT)

// ---------------- complex helpers ----------------
__device__ __forceinline__ float2 cadd(float2 a, float2 b) { return make_float2(a.x + b.x, a.y + b.y); }
__device__ __forceinline__ float2 csub(float2 a, float2 b) { return make_float2(a.x - b.x, a.y - b.y); }
__device__ __forceinline__ float2 cmul(float2 a, float2 b) {
    return make_float2(a.x * b.x - a.y * b.y, a.x * b.y + a.y * b.x);
}
__device__ __forceinline__ float2 cmulconj(float2 a, float2 w) {  // a * conj(w)
    return make_float2(a.x * w.x + a.y * w.y, a.y * w.x - a.x * w.y);
}

// ---------------- twiddle init ----------------
__global__ void k_twiddle() {
    int j = blockIdx.x * blockDim.x + threadIdx.x;
    if (j < NFFT) {
        float s, c;
        sincospif(-2.0f * (float)j / (float)NFFT, &s, &c);
        g_tw[j] = make_float2(c, s);
    }
}

// ---------------- in-place radix-4 DIF forward stages (shared) ----------------
__device__ __forceinline__ void fft_fwd_shared(float2* S, int tid) {
    #pragma unroll
    for (int s = 0; s < 6; s++) {
        int len = NFFT >> (2 * s);
        int q = len >> 2;
        int step = 1 << (2 * s);
        for (int idx = tid; idx < NFFT / 4; idx += 256) {
            int j = idx & (q - 1);
            int g = idx >> (10 - 2 * s);
            int base = (g << (12 - 2 * s)) + j;
            float2 a = S[base], b = S[base + q], c = S[base + 2 * q], d = S[base + 3 * q];
            float2 w1 = g_tw[j * step];
            float2 w2 = cmul(w1, w1);
            float2 w3 = cmul(w2, w1);
            float2 t0 = cadd(a, c), t1 = csub(a, c);
            float2 t2 = cadd(b, d), t3 = csub(b, d);
            float2 t3m = make_float2(t3.y, -t3.x);           // -i*(b-d)
            S[base]         = cadd(t0, t2);
            S[base + q]     = cmul(cadd(t1, t3m), w1);
            S[base + 2 * q] = cmul(csub(t0, t2), w2);
            S[base + 3 * q] = cmul(csub(t1, t3m), w3);
        }
        __syncthreads();
    }
}

// ---------------- in-place radix-4 DIT inverse stages (exact inverse of fwd) ----------------
__device__ __forceinline__ void fft_inv_shared(float2* S, int tid) {
    #pragma unroll
    for (int s = 5; s >= 0; s--) {
        int len = NFFT >> (2 * s);
        int q = len >> 2;
        int step = 1 << (2 * s);
        for (int idx = tid; idx < NFFT / 4; idx += 256) {
            int j = idx & (q - 1);
            int g = idx >> (10 - 2 * s);
            int base = (g << (12 - 2 * s)) + j;
            float2 w1 = g_tw[j * step];
            float2 w2 = cmul(w1, w1);
            float2 w3 = cmul(w2, w1);
            float2 u0 = S[base];
            float2 u1 = cmulconj(S[base + q], w1);
            float2 u2 = cmulconj(S[base + 2 * q], w2);
            float2 u3 = cmulconj(S[base + 3 * q], w3);
            float2 t0 = cadd(u0, u2), t1 = csub(u0, u2);
            float2 t2 = cadd(u1, u3), t3 = csub(u1, u3);
            float2 it3 = make_float2(-t3.y, t3.x);           // i*(u1-u3)
            S[base]         = cadd(t0, t2);
            S[base + q]     = cadd(t1, it3);
            S[base + 2 * q] = csub(t0, t2);
            S[base + 3 * q] = csub(t1, it3);
        }
        __syncthreads();
    }
}

// ---------------- forward FFT: 768 x-channels (packed +/-) + 16 phi channels ----------------
__global__ void __launch_bounds__(256) k_fft_fwd(const float* __restrict__ x,
                                                 const float* __restrict__ phi) {
    __shared__ float2 S[NFFT];
    int b = blockIdx.x;
    int tid = threadIdx.x;
    if (b < D_DIM) {
        int d = b;
        for (int t = tid; t < NFFT; t += 256) {
            float v = (t < L_SEQ) ? x[t * D_DIM + d] : 0.0f;
            float sg = (t & 1) ? -v : v;
            S[t] = make_float2(v, sg);
        }
    } else {
        int k = b - D_DIM;
        for (int t = tid; t < NFFT; t += 256)
            S[t] = make_float2((t < L_SEQ) ? phi[t * K_F + k] : 0.0f, 0.0f);
    }
    __syncthreads();
    fft_fwd_shared(S, tid);
    float2* out = (b < D_DIM) ? (g_Z + (size_t)b * NFFT) : (g_V + (size_t)(b - D_DIM) * NFFT);
    for (int t = tid; t < NFFT; t += 256) out[t] = S[t];
}

// ---------------- per-(k,d): pointwise V*Z, inverse FFT, scatter to Ubig ----------------
__global__ void __launch_bounds__(256) k_conv_inv() {
    __shared__ float2 S[NFFT];
    int b = blockIdx.x;              // 0 .. K_F*D_DIM-1
    int k = b / D_DIM;
    int d = b - k * D_DIM;
    int tid = threadIdx.x;
    const float2* Z = g_Z + (size_t)d * NFFT;
    const float2* V = g_V + (size_t)k * NFFT;
    for (int t = tid; t < NFFT; t += 256) S[t] = cmul(Z[t], V[t]);
    __syncthreads();
    fft_inv_shared(S, tid);
    const float inv = 1.0f / (float)NFFT;
    float* up = g_Ubig + (size_t)(k * D_DIM + d) * L_SEQ;
    float* um = g_Ubig + (size_t)(C_CONV / 2 + k * D_DIM + d) * L_SEQ;
    for (int t = tid; t < L_SEQ; t += 256) {
        float2 v = S[t];
        up[t] = v.x * inv;
        um[t] = ((t & 1) ? -v.y : v.y) * inv;
    }
}

// ---------------- AR channels: Ubig rows 24576.. hold shifted x ----------------
__global__ void __launch_bounds__(256) k_arfill(const float* __restrict__ x) {
    int c = blockIdx.x;              // 0 .. KU*D_DIM-1
    int i = c / D_DIM;
    int d = c - i * D_DIM;
    float* dst = g_Ubig + (size_t)(C_CONV + c) * L_SEQ;
    for (int l = threadIdx.x; l < L_SEQ; l += 256)
        dst[l] = (l >= i) ? x[(l - i) * D_DIM + d] : 0.0f;
}

// ---------------- pack [Mp*sig4 ; Mm*sig4 ; Mu] into (C_TOT, D) ----------------
__global__ void __launch_bounds__(256) k_mbig(const float* __restrict__ Mp,
                                              const float* __restrict__ Mm,
                                              const float* __restrict__ Mu,
                                              const float* __restrict__ sigma) {
    int c = blockIdx.x;
    const float* src;
    float scale;
    if (c < K_F * D_DIM) {
        int k = c / D_DIM;
        src = Mp + (size_t)c * D_DIM;
        scale = powf(sigma[k], 0.25f);
    } else if (c < 2 * K_F * D_DIM) {
        int cc = c - K_F * D_DIM;
        int k = cc / D_DIM;
        src = Mm + (size_t)cc * D_DIM;
        scale = powf(sigma[k], 0.25f);
    } else {
        int cc = c - 2 * K_F * D_DIM;
        src = Mu + (size_t)cc * D_DIM;
        scale = 1.0f;
    }
    for (int o = threadIdx.x; o < D_DIM; o += 256)
        g_Mbig[(size_t)c * D_DIM + o] = src[o] * scale;
}

// ---------------- TF32 GEMM: out[l,o] = sum_c Ubig[c,l] * Mbig[c,o] ----------------
__device__ __forceinline__ float to_tf32(float x) {
    float r;
    asm("cvt.rna.tf32.f32 %0, %1;" : "=f"(r) : "f"(x));
    return r;
}
__device__ __forceinline__ void mma_tf32(float* acc, const uint32_t* a, const uint32_t* b) {
    asm volatile(
        "mma.sync.aligned.m16n8k8.row.col.f32.tf32.tf32.f32 "
        "{%0,%1,%2,%3}, {%4,%5,%6,%7}, {%8,%9}, {%0,%1,%2,%3};"
        : "+f"(acc[0]), "+f"(acc[1]), "+f"(acc[2]), "+f"(acc[3])
        : "r"(a[0]), "r"(a[1]), "r"(a[2]), "r"(a[3]), "r"(b[0]), "r"(b[1]));
}

__global__ void __launch_bounds__(128) k_gemm(float* __restrict__ out) {
    __shared__ float As[32][72];  // [c][l], pitch 72 -> conflict-free fragment LDS
    __shared__ float Bs[32][72];  // [c][o]
    const int tid = threadIdx.x;
    const int lane = tid & 31, warp = tid >> 5;
    const int mbase = blockIdx.y * 64, nbase = blockIdx.x * 64;
    const int wm = (warp & 1) * 32, wn = (warp >> 1) * 32;
    const int row = lane >> 2, col = lane & 3;
    const int cl = tid >> 4;          // loader: base c row
    const int l4 = (tid & 15) * 4;    // loader: float4 offset within row

    float acc[2][4][4];
    #pragma unroll
    for (int mi = 0; mi < 2; mi++)
        #pragma unroll
        for (int ni = 0; ni < 4; ni++)
            #pragma unroll
            for (int r = 0; r < 4; r++) acc[mi][ni][r] = 0.0f;

    float4 ra[4], rb[4];

    auto LOADG = [&](int kt) {
        int kb = kt * 32;
        #pragma unroll
        for (int i = 0; i < 4; i++) {
            int c = cl + i * 8;
            ra[i] = *(const float4*)(g_Ubig + (size_t)(kb + c) * L_SEQ + mbase + l4);
            rb[i] = *(const float4*)(g_Mbig + (size_t)(kb + c) * D_DIM + nbase + l4);
        }
    };
    auto STORES = [&]() {
        #pragma unroll
        for (int i = 0; i < 4; i++) {
            int c = cl + i * 8;
            As[c][l4 + 0] = to_tf32(ra[i].x); As[c][l4 + 1] = to_tf32(ra[i].y);
            As[c][l4 + 2] = to_tf32(ra[i].z); As[c][l4 + 3] = to_tf32(ra[i].w);
            Bs[c][l4 + 0] = to_tf32(rb[i].x); Bs[c][l4 + 1] = to_tf32(rb[i].y);
            Bs[c][l4 + 2] = to_tf32(rb[i].z); Bs[c][l4 + 3] = to_tf32(rb[i].w);
        }
    };

    LOADG(0);
    STORES();
    __syncthreads();

    for (int kt = 0; kt < KTILES; kt++) {
        if (kt + 1 < KTILES) LOADG(kt + 1);
        #pragma unroll
        for (int ks = 0; ks < 4; ks++) {
            const int k8 = ks * 8;
            uint32_t a[2][4], bf[4][2];
            #pragma unroll
            for (int mi = 0; mi < 2; mi++) {
                int lb = wm + mi * 16 + row;
                a[mi][0] = __float_as_uint(As[k8 + col][lb]);
                a[mi][1] = __float_as_uint(As[k8 + col][lb + 8]);
                a[mi][2] = __float_as_uint(As[k8 + col + 4][lb]);
                a[mi][3] = __float_as_uint(As[k8 + col + 4][lb + 8]);
            }
            #pragma unroll
            for (int ni = 0; ni < 4; ni++) {
                int nb = wn + ni * 8 + row;
                bf[ni][0] = __float_as_uint(Bs[k8 + col][nb]);
                bf[ni][1] = __float_as_uint(Bs[k8 + col + 4][nb]);
            }
            #pragma unroll
            for (int mi = 0; mi < 2; mi++)
                #pragma unroll
                for (int ni = 0; ni < 4; ni++)
                    mma_tf32(acc[mi][ni], a[mi], bf[ni]);
        }
        __syncthreads();
        if (kt + 1 < KTILES) {
            STORES();
            __syncthreads();
        }
    }

    // epilogue: D = spectral + ar, row-major (L, D)
    #pragma unroll
    for (int mi = 0; mi < 2; mi++) {
        #pragma unroll
        for (int ni = 0; ni < 4; ni++) {
            int r0 = mbase + wm + mi * 16 + row;
            int c0 = nbase + wn + ni * 8 + col * 2;
            out[(size_t)r0 * D_DIM + c0]           = acc[mi][ni][0];
            out[(size_t)r0 * D_DIM + c0 + 1]       = acc[mi][ni][1];
            out[(size_t)(r0 + 8) * D_DIM + c0]     = acc[mi][ni][2];
            out[(size_t)(r0 + 8) * D_DIM + c0 + 1] = acc[mi][ni][3];
        }
    }
}

// ---------------- launch ----------------
extern "C" void kernel_launch(void* const* d_in, const int* in_sizes, int n_in,
                              void* d_out, int out_size) {
    const float* x     = (const float*)d_in[0];
    const float* phi   = (const float*)d_in[1];
    const float* sigma = (const float*)d_in[2];
    const float* Mp    = (const float*)d_in[3];
    const float* Mm    = (const float*)d_in[4];
    const float* Mu    = (const float*)d_in[5];
    (void)in_sizes; (void)n_in; (void)out_size;

    k_twiddle<<<NFFT / 256, 256>>>();
    k_fft_fwd<<<D_DIM + K_F, 256>>>(x, phi);
    k_conv_inv<<<K_F * D_DIM, 256>>>();
    k_arfill<<<KU * D_DIM, 256>>>(x);
    k_mbig<<<C_TOT, 256>>>(Mp, Mm, Mu, sigma);
    k_gemm<<<dim3(D_DIM / 64, L_SEQ / 64), 128>>>((float*)d_out);
}